// round 3
// baseline (speedup 1.0000x reference)
#include <cuda_runtime.h>
#include <math.h>

#define H  1024
#define B  64
#define L  1024
#define VP 32000
#define VC 32000
#define LSP 16
#define LJ  (L / LSP)
#define KC  16
#define TV  128
#define NTILE (H / KC)

typedef unsigned long long ull;

// ---- scratch (device globals; no allocation allowed) ----
__device__ __align__(16) float g_hnew[B * H];
__device__ __align__(16) float g_scores[B * L];
__device__ __align__(16) float g_ctxpart[B * LSP * H];
__device__ float g_pm[B * LSP];
__device__ float g_ps[B * LSP];
__device__ __align__(16) float g_ctx[B * H];
__device__ __align__(16) float g_concatT[H * B];   // [k][b], feeds logits GEMM

__device__ __forceinline__ float warp_sum(float v) {
#pragma unroll
    for (int o = 16; o; o >>= 1) v += __shfl_xor_sync(0xffffffffu, v, o);
    return v;
}

__device__ __forceinline__ ull pack2(float a, float b) {
    ull r; asm("mov.b64 %0, {%1,%2};" : "=l"(r) : "f"(a), "f"(b)); return r;
}
__device__ __forceinline__ void unpack2(ull v, float& a, float& b) {
    asm("mov.b64 {%0,%1}, %2;" : "=f"(a), "=f"(b) : "l"(v));
}
__device__ __forceinline__ ull fma2(ull a, ull b, ull c) {
    ull d; asm("fma.rn.f32x2 %0, %1, %2, %3;" : "=l"(d) : "l"(a), "l"(b), "l"(c));
    return d;
}

// ---------------------------------------------------------------------------
// 1) Fused GRU step: one block per hidden index i.
// ---------------------------------------------------------------------------
__global__ void gru_kernel(const int* __restrict__ seq,
                           const float* __restrict__ hprev,
                           const float* __restrict__ emb,
                           const float* __restrict__ w_ih,
                           const float* __restrict__ w_hh,
                           const float* __restrict__ b_ih,
                           const float* __restrict__ b_hh,
                           float* __restrict__ hidden_out) {
    int i = blockIdx.x;
    __shared__ float sw[6][H];
    for (int k = threadIdx.x; k < H; k += blockDim.x) {
        sw[0][k] = w_ih[(size_t)i * H + k];
        sw[1][k] = w_ih[(size_t)(i + H) * H + k];
        sw[2][k] = w_ih[(size_t)(i + 2 * H) * H + k];
        sw[3][k] = w_hh[(size_t)i * H + k];
        sw[4][k] = w_hh[(size_t)(i + H) * H + k];
        sw[5][k] = w_hh[(size_t)(i + 2 * H) * H + k];
    }
    __syncthreads();

    int wid = threadIdx.x >> 5, lane = threadIdx.x & 31;
#pragma unroll
    for (int t = 0; t < 8; t++) {
        int b = wid + 8 * t;
        const float* xr = emb + (size_t)seq[b] * H;
        const float* hr = hprev + (size_t)b * H;
        float sir = 0.f, siz = 0.f, sin_ = 0.f, shr = 0.f, shz = 0.f, shn = 0.f;
        for (int k = lane; k < H; k += 32) {
            float xv = xr[k], hv = hr[k];
            sir += xv * sw[0][k]; siz += xv * sw[1][k]; sin_ += xv * sw[2][k];
            shr += hv * sw[3][k]; shz += hv * sw[4][k]; shn += hv * sw[5][k];
        }
        sir = warp_sum(sir); siz = warp_sum(siz); sin_ = warp_sum(sin_);
        shr = warp_sum(shr); shz = warp_sum(shz); shn = warp_sum(shn);
        if (lane == 0) {
            float gr = sir + b_ih[i] + shr + b_hh[i];
            float gz = siz + b_ih[i + H] + shz + b_hh[i + H];
            float r = 1.f / (1.f + expf(-gr));
            float z = 1.f / (1.f + expf(-gz));
            float n = tanhf(sin_ + b_ih[i + 2 * H] + r * (shn + b_hh[i + 2 * H]));
            float hv = hprev[(size_t)b * H + i];
            float hn = (1.f - z) * n + z * hv;
            g_hnew[b * H + i] = hn;
            hidden_out[b * H + i] = hn;
        }
    }
}

// ---------------------------------------------------------------------------
// 2) Flash attention: one pass over enc. Block (b, c) handles 64 l's.
//    Running max/sum rescaling; also stores raw scores for the attn output.
// ---------------------------------------------------------------------------
__global__ __launch_bounds__(256) void flash_attn_kernel(const float* __restrict__ enc) {
    int b = blockIdx.x, c = blockIdx.y;
    int tid = threadIdx.x;
    float4 h4 = ((const float4*)(g_hnew + (size_t)b * H))[tid];

    __shared__ float red[8];
    __shared__ float bcast;

    float m = -1e30f, s = 0.f;
    float4 acc = make_float4(0.f, 0.f, 0.f, 0.f);

    for (int j = 0; j < LJ; j++) {
        int l = c * LJ + j;
        float4 e = ((const float4*)(enc + ((size_t)l * B + b) * H))[tid];
        float d = e.x * h4.x + e.y * h4.y + e.z * h4.z + e.w * h4.w;
        d = warp_sum(d);
        if ((tid & 31) == 0) red[tid >> 5] = d;
        __syncthreads();
        if (tid == 0) {
            float t = red[0] + red[1] + red[2] + red[3]
                    + red[4] + red[5] + red[6] + red[7];
            bcast = t;
            g_scores[b * L + l] = t;
        }
        __syncthreads();
        float score = bcast;
        float nm = fmaxf(m, score);
        float scale = expf(m - nm);
        float p = expf(score - nm);
        s = s * scale + p;
        acc.x = acc.x * scale + p * e.x;
        acc.y = acc.y * scale + p * e.y;
        acc.z = acc.z * scale + p * e.z;
        acc.w = acc.w * scale + p * e.w;
        m = nm;
    }
    ((float4*)(g_ctxpart + ((size_t)(b * LSP + c)) * H))[tid] = acc;
    if (tid == 0) { g_pm[b * LSP + c] = m; g_ps[b * LSP + c] = s; }
}

// combine flash partials -> context
__global__ void ctx_combine_kernel() {
    int b = blockIdx.x, tid = threadIdx.x;
    __shared__ float sm[LSP], ss[LSP];
    if (tid < LSP) { sm[tid] = g_pm[b * LSP + tid]; ss[tid] = g_ps[b * LSP + tid]; }
    __syncthreads();
    float gm = -1e30f;
#pragma unroll
    for (int c = 0; c < LSP; c++) gm = fmaxf(gm, sm[c]);
    float S = 0.f;
    float4 a = make_float4(0.f, 0.f, 0.f, 0.f);
#pragma unroll
    for (int c = 0; c < LSP; c++) {
        float w = expf(sm[c] - gm);
        S += ss[c] * w;
        float4 p = ((const float4*)(g_ctxpart + ((size_t)(b * LSP + c)) * H))[tid];
        a.x += w * p.x; a.y += w * p.y; a.z += w * p.z; a.w += w * p.w;
    }
    float inv = 1.f / S;
    a.x *= inv; a.y *= inv; a.z *= inv; a.w *= inv;
    ((float4*)(g_ctx + (size_t)b * H))[tid] = a;
}

// ---------------------------------------------------------------------------
// 3) softmax over L per batch row -> attn weights output
// ---------------------------------------------------------------------------
__global__ void softmax_kernel(float* __restrict__ attn_out) {
    int b = blockIdx.x, tid = threadIdx.x;
    __shared__ float sh[8];
    __shared__ float sval;

    float m = -1e30f;
    for (int l = tid; l < L; l += 256) m = fmaxf(m, g_scores[b * L + l]);
#pragma unroll
    for (int o = 16; o; o >>= 1) m = fmaxf(m, __shfl_xor_sync(0xffffffffu, m, o));
    if ((tid & 31) == 0) sh[tid >> 5] = m;
    __syncthreads();
    if (tid == 0) {
        float mm = sh[0];
        for (int j = 1; j < 8; j++) mm = fmaxf(mm, sh[j]);
        sval = mm;
    }
    __syncthreads();
    m = sval;

    float s = 0.f;
    for (int l = tid; l < L; l += 256) s += expf(g_scores[b * L + l] - m);
    s = warp_sum(s);
    __syncthreads();
    if ((tid & 31) == 0) sh[tid >> 5] = s;
    __syncthreads();
    if (tid == 0) {
        float ss = 0.f;
        for (int j = 0; j < 8; j++) ss += sh[j];
        sval = ss;
    }
    __syncthreads();
    float inv = 1.f / sval;

    for (int l = tid; l < L; l += 256)
        attn_out[b * L + l] = expf(g_scores[b * L + l] - m) * inv;
}

// ---------------------------------------------------------------------------
// 4) concat_output = tanh([h_new|context] @ concat_w.T + concat_b)
//    writes TRANSPOSED g_concatT[i][b] for the logits GEMM.
// ---------------------------------------------------------------------------
__global__ void concat_kernel(const float* __restrict__ cw,
                              const float* __restrict__ cb) {
    int i = blockIdx.x;
    __shared__ float sw[2 * H];
    for (int k = threadIdx.x; k < 2 * H; k += blockDim.x)
        sw[k] = cw[(size_t)i * 2 * H + k];
    __syncthreads();
    int wid = threadIdx.x >> 5, lane = threadIdx.x & 31;
#pragma unroll
    for (int t = 0; t < 8; t++) {
        int b = wid + 8 * t;
        const float* hr = g_hnew + b * H;
        const float* cr = g_ctx + b * H;
        float s = 0.f;
        for (int k = lane; k < H; k += 32)
            s += hr[k] * sw[k] + cr[k] * sw[k + H];
        s = warp_sum(s);
        if (lane == 0) g_concatT[(size_t)i * B + b] = tanhf(s + cb[i]);
    }
}

// ---------------------------------------------------------------------------
// 5) vocab logits: double-buffered register-tiled SGEMM, packed f32x2 FMA.
//    Block = 128 vocab x 64 batch, KC=16, 2-stage smem pipeline.
// ---------------------------------------------------------------------------
__global__ __launch_bounds__(256) void logits_gemm(
        const float* __restrict__ wp, const float* __restrict__ bp,
        const float* __restrict__ wc, const float* __restrict__ bc,
        float* __restrict__ out) {
    int v0 = blockIdx.x * TV;
    const float* W; const float* bias; float* obase;
    if (v0 < VP) { W = wp; bias = bp; obase = out; }
    else { W = wc; bias = bc; obase = out + (size_t)B * VP; v0 -= VP; }

    __shared__ float Wt[2][KC][TV];     // k-major W tile
    __shared__ ull   Xp[2][KC][B];      // pre-duplicated f32x2 X tile

    int t = threadIdx.x;
    int tx = t & 15;          // b-group: b = tx*4 .. tx*4+3
    int ty = t >> 4;          // v-group: v = ty*8 .. ty*8+7

    // loader indices
    int wv = t >> 2;          // 0..63?  no: 256 threads, 2 float4 each
    int wq = t & 3;
    int xk = t >> 4;          // 0..15
    int xb = t & 15;          // float4 within row

    ull acc[4][4];
#pragma unroll
    for (int i = 0; i < 4; i++)
#pragma unroll
        for (int j = 0; j < 4; j++) acc[i][j] = 0ull;

    float4 wpre[2];
    float4 xpre;

    // ---- prime stage 0 ----
    {
        int kc = 0;
#pragma unroll
        for (int r = 0; r < 2; r++) {
            int f = t + r * 256;          // 0..511 float4 ids
            int v = f >> 2, kq = f & 3;
            float4 w4 = *(const float4*)(W + (size_t)(v0 + v) * H + kc + kq * 4);
            Wt[0][kq * 4 + 0][v] = w4.x;
            Wt[0][kq * 4 + 1][v] = w4.y;
            Wt[0][kq * 4 + 2][v] = w4.z;
            Wt[0][kq * 4 + 3][v] = w4.w;
        }
        float4 x4 = *(const float4*)(g_concatT + (size_t)(kc + xk) * B + xb * 4);
        Xp[0][xk][xb * 4 + 0] = pack2(x4.x, x4.x);
        Xp[0][xk][xb * 4 + 1] = pack2(x4.y, x4.y);
        Xp[0][xk][xb * 4 + 2] = pack2(x4.z, x4.z);
        Xp[0][xk][xb * 4 + 3] = pack2(x4.w, x4.w);
    }
    __syncthreads();

    for (int tile = 0; tile < NTILE; tile++) {
        int cur = tile & 1;
        // prefetch next tile into regs
        if (tile + 1 < NTILE) {
            int kc = (tile + 1) * KC;
#pragma unroll
            for (int r = 0; r < 2; r++) {
                int f = t + r * 256;
                int v = f >> 2, kq = f & 3;
                wpre[r] = *(const float4*)(W + (size_t)(v0 + v) * H + kc + kq * 4);
            }
            xpre = *(const float4*)(g_concatT + (size_t)(kc + xk) * B + xb * 4);
        }

        // compute current tile
#pragma unroll
        for (int k = 0; k < KC; k++) {
            ulonglong2 wl = *(const ulonglong2*)&Wt[cur][k][ty * 8];
            ulonglong2 wh = *(const ulonglong2*)&Wt[cur][k][ty * 8 + 4];
            ulonglong2 x01 = *(const ulonglong2*)&Xp[cur][k][tx * 4];
            ulonglong2 x23 = *(const ulonglong2*)&Xp[cur][k][tx * 4 + 2];
            acc[0][0] = fma2(wl.x, x01.x, acc[0][0]);
            acc[0][1] = fma2(wl.x, x01.y, acc[0][1]);
            acc[0][2] = fma2(wl.x, x23.x, acc[0][2]);
            acc[0][3] = fma2(wl.x, x23.y, acc[0][3]);
            acc[1][0] = fma2(wl.y, x01.x, acc[1][0]);
            acc[1][1] = fma2(wl.y, x01.y, acc[1][1]);
            acc[1][2] = fma2(wl.y, x23.x, acc[1][2]);
            acc[1][3] = fma2(wl.y, x23.y, acc[1][3]);
            acc[2][0] = fma2(wh.x, x01.x, acc[2][0]);
            acc[2][1] = fma2(wh.x, x01.y, acc[2][1]);
            acc[2][2] = fma2(wh.x, x23.x, acc[2][2]);
            acc[2][3] = fma2(wh.x, x23.y, acc[2][3]);
            acc[3][0] = fma2(wh.y, x01.x, acc[3][0]);
            acc[3][1] = fma2(wh.y, x01.y, acc[3][1]);
            acc[3][2] = fma2(wh.y, x23.x, acc[3][2]);
            acc[3][3] = fma2(wh.y, x23.y, acc[3][3]);
        }

        // store prefetched into other buffer
        if (tile + 1 < NTILE) {
            int nxt = cur ^ 1;
#pragma unroll
            for (int r = 0; r < 2; r++) {
                int f = t + r * 256;
                int v = f >> 2, kq = f & 3;
                Wt[nxt][kq * 4 + 0][v] = wpre[r].x;
                Wt[nxt][kq * 4 + 1][v] = wpre[r].y;
                Wt[nxt][kq * 4 + 2][v] = wpre[r].z;
                Wt[nxt][kq * 4 + 3][v] = wpre[r].w;
            }
            Xp[nxt][xk][xb * 4 + 0] = pack2(xpre.x, xpre.x);
            Xp[nxt][xk][xb * 4 + 1] = pack2(xpre.y, xpre.y);
            Xp[nxt][xk][xb * 4 + 2] = pack2(xpre.z, xpre.z);
            Xp[nxt][xk][xb * 4 + 3] = pack2(xpre.w, xpre.w);
        }
        __syncthreads();
    }

    // epilogue: out[b][v] (+bias), float2 stores over consecutive v
#pragma unroll
    for (int vi2 = 0; vi2 < 4; vi2++) {
        int gv = v0 + ty * 8 + vi2 * 2;
        float b0 = bias[gv], b1 = bias[gv + 1];
#pragma unroll
        for (int bj = 0; bj < 4; bj++) {
            int b = tx * 4 + bj;
            float lo, hi; unpack2(acc[vi2][bj], lo, hi);
            float2 r2 = make_float2(lo + b0, hi + b1);
            *(float2*)(obase + (size_t)b * VP + gv) = r2;
        }
    }
}

// ---------------------------------------------------------------------------
extern "C" void kernel_launch(void* const* d_in, const int* in_sizes, int n_in,
                              void* d_out, int out_size) {
    const int*   seq         = (const int*)d_in[0];
    const float* last_hidden = (const float*)d_in[1];
    const float* enc         = (const float*)d_in[2];
    const float* emb         = (const float*)d_in[3];
    const float* w_ih        = (const float*)d_in[4];
    const float* w_hh        = (const float*)d_in[5];
    const float* b_ih        = (const float*)d_in[6];
    const float* b_hh        = (const float*)d_in[7];
    const float* concat_w    = (const float*)d_in[8];
    const float* concat_b    = (const float*)d_in[9];
    const float* owp         = (const float*)d_in[10];
    const float* obp         = (const float*)d_in[11];
    const float* owc         = (const float*)d_in[12];
    const float* obc         = (const float*)d_in[13];

    float* out        = (float*)d_out;
    float* out_hidden = out + (size_t)B * (VP + VC);   // [1,B,H]
    float* out_attn   = out_hidden + (size_t)B * H;    // [B,1,L]

    gru_kernel<<<H, 256>>>(seq, last_hidden, emb, w_ih, w_hh, b_ih, b_hh, out_hidden);
    flash_attn_kernel<<<dim3(B, LSP), 256>>>(enc);
    softmax_kernel<<<B, 256>>>(out_attn);
    ctx_combine_kernel<<<B, 256>>>();
    concat_kernel<<<H, 256>>>(concat_w, concat_b);
    logits_gemm<<<(VP + VC) / TV, 256>>>(owp, obp, owc, obc, out);
}

// round 5
// speedup vs baseline: 1.3303x; 1.3303x over previous
#include <cuda_runtime.h>
#include <math.h>
#include <stdint.h>

#define H  1024
#define B  64
#define L  1024
#define VP 32000
#define VC 32000
#define LSPLIT 16

// ---- logits MMA-GEMM config ----
#define TV   128          // vocab rows per block (M)
#define KC   16           // k per smem tile
#define NKT  (H / KC)     // 64 tiles
#define WROW 136          // padded W tile row (floats): conflict-free frag loads
#define XROW 72           // padded X tile row
// dynamic smem: Wt[2buf][2part][KC][WROW] then Xt[2][2][KC][XROW]
#define WT_FLOATS (2 * 2 * KC * WROW)
#define XT_FLOATS (2 * 2 * KC * XROW)
#define SM_TOTAL  ((WT_FLOATS + XT_FLOATS) * 4)

// ---- scratch ----
__device__ __align__(16) float g_hnew[B * H];
__device__ __align__(16) float g_scores[B * L];
__device__ __align__(16) float g_attn[B * L];
__device__ __align__(16) float g_ctxpart[B * LSPLIT * H];
__device__ __align__(16) float g_ctx[B * H];
__device__ __align__(16) float g_concat[B * H];   // [b][k]

__device__ __forceinline__ float warp_sum(float v) {
#pragma unroll
    for (int o = 16; o; o >>= 1) v += __shfl_xor_sync(0xffffffffu, v, o);
    return v;
}
__device__ __forceinline__ uint32_t f2tf32(float x) {
    uint32_t u; asm("cvt.rna.tf32.f32 %0, %1;" : "=r"(u) : "f"(x)); return u;
}
__device__ __forceinline__ void mma_tf32(float* c, const uint32_t* a,
                                         uint32_t b0, uint32_t b1) {
    asm volatile(
        "mma.sync.aligned.m16n8k8.row.col.f32.tf32.tf32.f32 "
        "{%0,%1,%2,%3}, {%4,%5,%6,%7}, {%8,%9}, {%0,%1,%2,%3};"
        : "+f"(c[0]), "+f"(c[1]), "+f"(c[2]), "+f"(c[3])
        : "r"(a[0]), "r"(a[1]), "r"(a[2]), "r"(a[3]), "r"(b0), "r"(b1));
}

// ---------------------------------------------------------------------------
// 1) Fused GRU step
// ---------------------------------------------------------------------------
__global__ void gru_kernel(const int* __restrict__ seq,
                           const float* __restrict__ hprev,
                           const float* __restrict__ emb,
                           const float* __restrict__ w_ih,
                           const float* __restrict__ w_hh,
                           const float* __restrict__ b_ih,
                           const float* __restrict__ b_hh,
                           float* __restrict__ hidden_out) {
    int i = blockIdx.x;
    __shared__ float sw[6][H];
    for (int k = threadIdx.x; k < H; k += blockDim.x) {
        sw[0][k] = w_ih[(size_t)i * H + k];
        sw[1][k] = w_ih[(size_t)(i + H) * H + k];
        sw[2][k] = w_ih[(size_t)(i + 2 * H) * H + k];
        sw[3][k] = w_hh[(size_t)i * H + k];
        sw[4][k] = w_hh[(size_t)(i + H) * H + k];
        sw[5][k] = w_hh[(size_t)(i + 2 * H) * H + k];
    }
    __syncthreads();
    int wid = threadIdx.x >> 5, lane = threadIdx.x & 31;
#pragma unroll
    for (int t = 0; t < 8; t++) {
        int b = wid + 8 * t;
        const float* xr = emb + (size_t)seq[b] * H;
        const float* hr = hprev + (size_t)b * H;
        float sir = 0.f, siz = 0.f, sin_ = 0.f, shr = 0.f, shz = 0.f, shn = 0.f;
        for (int k = lane; k < H; k += 32) {
            float xv = xr[k], hv = hr[k];
            sir += xv * sw[0][k]; siz += xv * sw[1][k]; sin_ += xv * sw[2][k];
            shr += hv * sw[3][k]; shz += hv * sw[4][k]; shn += hv * sw[5][k];
        }
        sir = warp_sum(sir); siz = warp_sum(siz); sin_ = warp_sum(sin_);
        shr = warp_sum(shr); shz = warp_sum(shz); shn = warp_sum(shn);
        if (lane == 0) {
            float gr = sir + b_ih[i] + shr + b_hh[i];
            float gz = siz + b_ih[i + H] + shz + b_hh[i + H];
            float r = 1.f / (1.f + expf(-gr));
            float z = 1.f / (1.f + expf(-gz));
            float n = tanhf(sin_ + b_ih[i + 2 * H] + r * (shn + b_hh[i + 2 * H]));
            float hv = hprev[(size_t)b * H + i];
            float hn = (1.f - z) * n + z * hv;
            g_hnew[b * H + i] = hn;
            hidden_out[b * H + i] = hn;
        }
    }
}

// ---------------------------------------------------------------------------
// 2) scores
// ---------------------------------------------------------------------------
__global__ void scores_kernel(const float* __restrict__ enc) {
    int l = blockIdx.x;
    int wid = threadIdx.x >> 5, lane = threadIdx.x & 31;
    const float4* encl = (const float4*)(enc + (size_t)l * B * H);
#pragma unroll
    for (int t = 0; t < 8; t++) {
        int b = wid + 8 * t;
        const float4* er = encl + (size_t)b * (H / 4);
        const float4* hr = (const float4*)g_hnew + (size_t)b * (H / 4);
        float s = 0.f;
        for (int k = lane; k < H / 4; k += 32) {
            float4 e = er[k], h = hr[k];
            s += e.x * h.x + e.y * h.y + e.z * h.z + e.w * h.w;
        }
        s = warp_sum(s);
        if (lane == 0) g_scores[b * L + l] = s;
    }
}

// ---------------------------------------------------------------------------
// 3) softmax
// ---------------------------------------------------------------------------
__global__ void softmax_kernel(float* __restrict__ attn_out) {
    int b = blockIdx.x, tid = threadIdx.x;
    __shared__ float sh[8];
    __shared__ float sval;
    float m = -1e30f;
    for (int l = tid; l < L; l += 256) m = fmaxf(m, g_scores[b * L + l]);
#pragma unroll
    for (int o = 16; o; o >>= 1) m = fmaxf(m, __shfl_xor_sync(0xffffffffu, m, o));
    if ((tid & 31) == 0) sh[tid >> 5] = m;
    __syncthreads();
    if (tid == 0) {
        float mm = sh[0];
        for (int j = 1; j < 8; j++) mm = fmaxf(mm, sh[j]);
        sval = mm;
    }
    __syncthreads();
    m = sval;
    float s = 0.f;
    for (int l = tid; l < L; l += 256) s += expf(g_scores[b * L + l] - m);
    s = warp_sum(s);
    __syncthreads();
    if ((tid & 31) == 0) sh[tid >> 5] = s;
    __syncthreads();
    if (tid == 0) {
        float ss = 0.f;
        for (int j = 0; j < 8; j++) ss += sh[j];
        sval = ss;
    }
    __syncthreads();
    float inv = 1.f / sval;
    for (int l = tid; l < L; l += 256) {
        float w = expf(g_scores[b * L + l] - m) * inv;
        g_attn[b * L + l] = w;
        attn_out[b * L + l] = w;
    }
}

// ---------------------------------------------------------------------------
// 4) context partials + reduce
// ---------------------------------------------------------------------------
__global__ void ctx_part_kernel(const float* __restrict__ enc) {
    int b = blockIdx.x, c = blockIdx.y;
    int tid = threadIdx.x;
    float4 a = make_float4(0.f, 0.f, 0.f, 0.f);
    int l0 = c * (L / LSPLIT);
    for (int j = 0; j < L / LSPLIT; j++) {
        int l = l0 + j;
        float w = g_attn[b * L + l];
        float4 e = ((const float4*)(enc + (size_t)l * B * H + (size_t)b * H))[tid];
        a.x += w * e.x; a.y += w * e.y; a.z += w * e.z; a.w += w * e.w;
    }
    ((float4*)(g_ctxpart + ((size_t)(b * LSPLIT + c)) * H))[tid] = a;
}

__global__ void ctx_reduce_kernel() {
    int b = blockIdx.x, tid = threadIdx.x;
    float4 s = make_float4(0.f, 0.f, 0.f, 0.f);
#pragma unroll
    for (int c = 0; c < LSPLIT; c++) {
        float4 p = ((const float4*)(g_ctxpart + ((size_t)(b * LSPLIT + c)) * H))[tid];
        s.x += p.x; s.y += p.y; s.z += p.z; s.w += p.w;
    }
    ((float4*)(g_ctx + (size_t)b * H))[tid] = s;
}

// ---------------------------------------------------------------------------
// 5) concat -> g_concat[b][i]
// ---------------------------------------------------------------------------
__global__ void concat_kernel(const float* __restrict__ cw,
                              const float* __restrict__ cb) {
    int i = blockIdx.x;
    __shared__ float sw[2 * H];
    for (int k = threadIdx.x; k < 2 * H; k += blockDim.x)
        sw[k] = cw[(size_t)i * 2 * H + k];
    __syncthreads();
    int wid = threadIdx.x >> 5, lane = threadIdx.x & 31;
#pragma unroll
    for (int t = 0; t < 8; t++) {
        int b = wid + 8 * t;
        const float* hr = g_hnew + b * H;
        const float* cr = g_ctx + b * H;
        float s = 0.f;
        for (int k = lane; k < H; k += 32)
            s += hr[k] * sw[k] + cr[k] * sw[k + H];
        s = warp_sum(s);
        if (lane == 0) g_concat[(size_t)b * H + i] = tanhf(s + cb[i]);
    }
}

// ---------------------------------------------------------------------------
// 6) logits: split-tf32 mma.sync GEMM. Block = 128V x 64B, 8 warps (4Mx2N),
//    warp tile 32x32, KC=16 double-buffered smem with register prefetch.
//    W,X split into tf32 hi/lo; D = hi*hi + hi*lo + lo*hi (~fp32 accuracy).
// ---------------------------------------------------------------------------
__global__ __launch_bounds__(256) void logits_mma(
        const float* __restrict__ wp, const float* __restrict__ bp,
        const float* __restrict__ wc, const float* __restrict__ bc,
        float* __restrict__ out) {
    extern __shared__ float smf[];
    float* Wt = smf;                 // [buf][part][KC][WROW]
    float* Xt = smf + WT_FLOATS;     // [buf][part][KC][XROW]

    int tid = threadIdx.x;
    int wid = tid >> 5, lane = tid & 31;
    int grp = lane >> 2, tig = lane & 3;
    int warpM = wid & 3, warpN = wid >> 2;

    int v0 = blockIdx.x * TV;
    const float* W; const float* bias; float* obase;
    if (v0 < VP) { W = wp; bias = bp; obase = out; }
    else { W = wc; bias = bc; obase = out + (size_t)B * VP; v0 -= VP; }

#define WT(buf, part, k, v) Wt[(((buf) * 2 + (part)) * KC + (k)) * WROW + (v)]
#define XT(buf, part, k, b) Xt[(((buf) * 2 + (part)) * KC + (k)) * XROW + (b)]

    float acc[2][4][4];
#pragma unroll
    for (int i = 0; i < 2; i++)
#pragma unroll
        for (int j = 0; j < 4; j++)
#pragma unroll
            for (int q = 0; q < 4; q++) acc[i][j][q] = 0.f;

    // loader indices: W 2 float4/thread, X 1 float4/thread
    int wv0 = tid >> 2, wkq = tid & 3;           // + r*64 rows
    int xb = tid >> 2, xkq = tid & 3;

    // ---- prime buffer 0 ----
    {
#pragma unroll
        for (int r = 0; r < 2; r++) {
            int v = wv0 + r * 64;
            float4 w4 = *(const float4*)(W + (size_t)(v0 + v) * H + wkq * 4);
            float wv[4] = {w4.x, w4.y, w4.z, w4.w};
#pragma unroll
            for (int j = 0; j < 4; j++) {
                uint32_t hb = f2tf32(wv[j]);
                float hf = __uint_as_float(hb);
                WT(0, 0, wkq * 4 + j, v) = hf;
                WT(0, 1, wkq * 4 + j, v) = __uint_as_float(f2tf32(wv[j] - hf));
            }
        }
        float4 x4 = *(const float4*)(g_concat + (size_t)xb * H + xkq * 4);
        float xv[4] = {x4.x, x4.y, x4.z, x4.w};
#pragma unroll
        for (int j = 0; j < 4; j++) {
            uint32_t hb = f2tf32(xv[j]);
            float hf = __uint_as_float(hb);
            XT(0, 0, xkq * 4 + j, xb) = hf;
            XT(0, 1, xkq * 4 + j, xb) = __uint_as_float(f2tf32(xv[j] - hf));
        }
    }
    __syncthreads();

    for (int t = 0; t < NKT; t++) {
        int cur = t & 1;
        float4 wpre[2], xpre;
        if (t + 1 < NKT) {
            int kc = (t + 1) * KC;
#pragma unroll
            for (int r = 0; r < 2; r++)
                wpre[r] = *(const float4*)(W + (size_t)(v0 + wv0 + r * 64) * H + kc + wkq * 4);
            xpre = *(const float4*)(g_concat + (size_t)xb * H + kc + xkq * 4);
        }

        // ---- compute current tile ----
#pragma unroll
        for (int ks = 0; ks < KC / 8; ks++) {
            int k0 = ks * 8 + tig;
            uint32_t aH[2][4], aL[2][4];
#pragma unroll
            for (int mf = 0; mf < 2; mf++) {
                int m = warpM * 32 + mf * 16 + grp;
                aH[mf][0] = __float_as_uint(WT(cur, 0, k0, m));
                aH[mf][1] = __float_as_uint(WT(cur, 0, k0, m + 8));
                aH[mf][2] = __float_as_uint(WT(cur, 0, k0 + 4, m));
                aH[mf][3] = __float_as_uint(WT(cur, 0, k0 + 4, m + 8));
                aL[mf][0] = __float_as_uint(WT(cur, 1, k0, m));
                aL[mf][1] = __float_as_uint(WT(cur, 1, k0, m + 8));
                aL[mf][2] = __float_as_uint(WT(cur, 1, k0 + 4, m));
                aL[mf][3] = __float_as_uint(WT(cur, 1, k0 + 4, m + 8));
            }
#pragma unroll
            for (int nf = 0; nf < 4; nf++) {
                int n = warpN * 32 + nf * 8 + grp;
                uint32_t bH0 = __float_as_uint(XT(cur, 0, k0, n));
                uint32_t bH1 = __float_as_uint(XT(cur, 0, k0 + 4, n));
                uint32_t bL0 = __float_as_uint(XT(cur, 1, k0, n));
                uint32_t bL1 = __float_as_uint(XT(cur, 1, k0 + 4, n));
#pragma unroll
                for (int mf = 0; mf < 2; mf++) {
                    mma_tf32(acc[mf][nf], aH[mf], bH0, bH1);
                    mma_tf32(acc[mf][nf], aH[mf], bL0, bL1);
                    mma_tf32(acc[mf][nf], aL[mf], bH0, bH1);
                }
            }
        }

        // ---- store prefetched tile ----
        if (t + 1 < NKT) {
            int nxt = cur ^ 1;
#pragma unroll
            for (int r = 0; r < 2; r++) {
                int v = wv0 + r * 64;
                float wv[4] = {wpre[r].x, wpre[r].y, wpre[r].z, wpre[r].w};
#pragma unroll
                for (int j = 0; j < 4; j++) {
                    uint32_t hb = f2tf32(wv[j]);
                    float hf = __uint_as_float(hb);
                    WT(nxt, 0, wkq * 4 + j, v) = hf;
                    WT(nxt, 1, wkq * 4 + j, v) = __uint_as_float(f2tf32(wv[j] - hf));
                }
            }
            float xv[4] = {xpre.x, xpre.y, xpre.z, xpre.w};
#pragma unroll
            for (int j = 0; j < 4; j++) {
                uint32_t hb = f2tf32(xv[j]);
                float hf = __uint_as_float(hb);
                XT(nxt, 0, xkq * 4 + j, xb) = hf;
                XT(nxt, 1, xkq * 4 + j, xb) = __uint_as_float(f2tf32(xv[j] - hf));
            }
        }
        __syncthreads();
    }

    // ---- epilogue ----
#pragma unroll
    for (int mf = 0; mf < 2; mf++) {
        int vr = v0 + warpM * 32 + mf * 16 + grp;
        float b0 = bias[vr], b1 = bias[vr + 8];
#pragma unroll
        for (int nf = 0; nf < 4; nf++) {
            int bcol = warpN * 32 + nf * 8 + 2 * tig;
            obase[(size_t)bcol * VP + vr]           = acc[mf][nf][0] + b0;
            obase[(size_t)(bcol + 1) * VP + vr]     = acc[mf][nf][1] + b0;
            obase[(size_t)bcol * VP + vr + 8]       = acc[mf][nf][2] + b1;
            obase[(size_t)(bcol + 1) * VP + vr + 8] = acc[mf][nf][3] + b1;
        }
    }
#undef WT
#undef XT
}

// ---------------------------------------------------------------------------
extern "C" void kernel_launch(void* const* d_in, const int* in_sizes, int n_in,
                              void* d_out, int out_size) {
    const int*   seq         = (const int*)d_in[0];
    const float* last_hidden = (const float*)d_in[1];
    const float* enc         = (const float*)d_in[2];
    const float* emb         = (const float*)d_in[3];
    const float* w_ih        = (const float*)d_in[4];
    const float* w_hh        = (const float*)d_in[5];
    const float* b_ih        = (const float*)d_in[6];
    const float* b_hh        = (const float*)d_in[7];
    const float* concat_w    = (const float*)d_in[8];
    const float* concat_b    = (const float*)d_in[9];
    const float* owp         = (const float*)d_in[10];
    const float* obp         = (const float*)d_in[11];
    const float* owc         = (const float*)d_in[12];
    const float* obc         = (const float*)d_in[13];

    float* out        = (float*)d_out;
    float* out_hidden = out + (size_t)B * (VP + VC);   // [1,B,H]
    float* out_attn   = out_hidden + (size_t)B * H;    // [B,1,L]

    cudaFuncSetAttribute(logits_mma, cudaFuncAttributeMaxDynamicSharedMemorySize, SM_TOTAL);

    gru_kernel<<<H, 256>>>(seq, last_hidden, emb, w_ih, w_hh, b_ih, b_hh, out_hidden);
    scores_kernel<<<L, 256>>>(enc);
    softmax_kernel<<<B, 256>>>(out_attn);
    ctx_part_kernel<<<dim3(B, LSPLIT), 256>>>(enc);
    ctx_reduce_kernel<<<B, 256>>>();
    concat_kernel<<<H, 256>>>(concat_w, concat_b);
    logits_mma<<<(VP + VC) / TV, 256, SM_TOTAL>>>(owp, obp, owc, obc, out);
}